// round 14
// baseline (speedup 1.0000x reference)
#include <cuda_runtime.h>

// ---------------------------------------------------------------------------
// ScalarDotProductCriticNetworkV8 — fused kernel, 2 batches/CTA (R14).
//
// R14 = R8 (51.2us, best) + bilinear-form elimination of the k/q GEMM:
//   score[j,i] = states[i] @ M @ states[j]^T + sv[i] + su[j] + c0,
//   M = Wq^T Wk / sqrt(D)  (precomputed in prep; u,v,c0 handle biases).
// P1' computes T = states@M (1 LDG + 8 FMA2 per k-step vs 2+16) and P3'
// dots T[i]·states[j] from a row-major states copy. ~16% fewer instr,
// P1 weight stream halved. P2/P4/P5 byte-identical to R8.
// ---------------------------------------------------------------------------

#define ULL unsigned long long

#define PACK2(d, lo, hi) asm("mov.b64 %0, {%1, %2};" : "=l"(d) : "f"(lo), "f"(hi))
#define UNPACK2(lo, hi, v) asm("mov.b64 {%0, %1}, %2;" : "=f"(lo), "=f"(hi) : "l"(v))
#define FMA2(acc, a, b) asm("fma.rn.f32x2 %0, %1, %2, %0;" : "+l"(acc) : "l"(a), "l"(b))
#define TANHA(y, x) asm("tanh.approx.f32 %0, %1;" : "=f"(y) : "f"(x))

// Precomputed weights (scratch; filled by prep kernel each launch).
__device__ float g_M[112 * 128];     // [f][g]: (Wq^T Wk)/sqrt(D), cols 112-127 zero
__device__ float g_WvT[128 * 128];   // [f][c]
__device__ float g_W1T[128 * 64];    // [d][h]
__device__ float g_u[112];           // (bq^T Wk)/sqrt(D)
__device__ float g_v[112];           // (Wq^T bk)/sqrt(D)
__device__ float g_c0[1];            // (bq.bk)/sqrt(D)

__global__ void prep(const float* __restrict__ Wk, const float* __restrict__ Wq,
                     const float* __restrict__ Wv, const float* __restrict__ W1,
                     const float* __restrict__ bk, const float* __restrict__ bq) {
    int t = blockIdx.x * blockDim.x + threadIdx.x;
    int S = gridDim.x * blockDim.x;
    const float s = 0.08838834764831845f;   // 1/sqrt(128)
    for (int i = t; i < 112 * 128; i += S) {
        int f = i >> 7, c = i & 127;
        float acc = 0.f;
        if (c < 112) {
#pragma unroll 4
            for (int d = 0; d < 128; d++)
                acc = fmaf(Wq[d * 112 + f], Wk[d * 112 + c], acc);
            acc *= s;
        }
        g_M[i] = acc;
    }
    for (int i = t; i < 128 * 128; i += S) {
        int f = i >> 7, c = i & 127;
        g_WvT[i] = Wv[c * 128 + f];
    }
    for (int i = t; i < 128 * 64; i += S) {
        int d = i >> 6, h = i & 63;
        g_W1T[i] = W1[h * 128 + d];
    }
    if (t < 112) {
        float au = 0.f, av = 0.f;
        for (int d = 0; d < 128; d++) {
            au = fmaf(bq[d], Wk[d * 112 + t], au);
            av = fmaf(Wq[d * 112 + t], bk[d], av);
        }
        g_u[t] = au * s;
        g_v[t] = av * s;
    }
    if (t == 112) {
        float a = 0.f;
        for (int d = 0; d < 128; d++) a = fmaf(bq[d], bk[d], a);
        g_c0[0] = a * s;
    }
}

// Shared memory (floats), aliased regions (R8 map + T_s/stR/su/sv):
//  A @0 (5184):   P0-P2: stT[112][36]@0, actT[16][36]@4032, polT[16][36]@4608
//                 P4-P5: aw1[32][68]@0, adw1[32][68]@2176
//  B @5184 (9216): P1',P3': T_s[32][128]@5184
//                  P2,P4:   avoT[128][36]@5184, avdT[128][36]@9792
//  sw1[32][64]@14400, wt[32][17]@16448, w2s[64]@16992,
//  su[32]@17056, sv[32]@17088, stR[32][116]@17120
#define OFF_STT   0
#define OFF_ACTT  4032
#define OFF_POLT  4608
#define OFF_AW1   0
#define OFF_ADW1  2176
#define OFF_T     5184
#define OFF_AVO   5184
#define OFF_AVD   9792
#define OFF_SW1   14400
#define OFF_WT    16448
#define OFF_W2    16992
#define OFF_SU    17056
#define OFF_SV    17088
#define OFF_STR   17120
#define SMEM_FLOATS 20832
#define SMEM_BYTES  (SMEM_FLOATS * 4)

__global__ void __launch_bounds__(256, 2)
critic_kernel(const float* __restrict__ states,
              const float* __restrict__ policies,
              const float* __restrict__ actions,
              const float* __restrict__ bv,
              const float* __restrict__ W2,
              float* __restrict__ out,
              int out_size) {
    extern __shared__ float sm[];
    float* stT  = sm + OFF_STT;
    float* actT = sm + OFF_ACTT;
    float* polT = sm + OFF_POLT;
    float* aw1  = sm + OFF_AW1;
    float* adw1 = sm + OFF_ADW1;
    float* T_s  = sm + OFF_T;
    float* avoT = sm + OFF_AVO;
    float* avdT = sm + OFF_AVD;
    float* sw1  = sm + OFF_SW1;
    float* wt   = sm + OFF_WT;
    float* w2s  = sm + OFF_W2;
    float* su   = sm + OFF_SU;
    float* sv   = sm + OFF_SV;
    float* stR  = sm + OFF_STR;

    const int t = threadIdx.x;
    const int b0 = blockIdx.x * 2;

    // ---- phase 0: stage inputs (stT transposed + stR row-major) ----
    {
        const float* stb = states + b0 * (16 * 112);
        for (int idx = t; idx < 32 * 112; idx += 256) {
            int rg = idx / 112, kk = idx - rg * 112;
            float val = stb[idx];
            stT[kk * 36 + rg] = val;
            stR[rg * 116 + kk] = val;
        }
#pragma unroll
        for (int s2 = 0; s2 < 2; s2++) {
            int idx = t + 256 * s2;
            int bl = idx >> 8, rem = idx & 255, i = rem >> 4, a = rem & 15;
            actT[a * 36 + bl * 16 + i] = actions[b0 * 256 + idx];
            polT[a * 36 + bl * 16 + i] = policies[b0 * 256 + idx];
        }
        if (t < 64) w2s[t] = W2[t];
    }
    __syncthreads();

    const int c = t & 127, bl = t >> 7;
    const int rbase = bl * 16;

    // ---- phase 1': T = states @ M (16 rows per thread), plus su/sv ----
    {
        ULL Ta[8] = {};
#pragma unroll 4
        for (int f = 0; f < 112; f++) {
            float w = g_M[f * 128 + c];
            ULL w2; PACK2(w2, w, w);
            const ulonglong2* sp = reinterpret_cast<const ulonglong2*>(stT + f * 36 + rbase);
#pragma unroll
            for (int p4 = 0; p4 < 4; p4++) {
                ulonglong2 svv = sp[p4];
                FMA2(Ta[2 * p4], w2, svv.x); FMA2(Ta[2 * p4 + 1], w2, svv.y);
            }
        }
#pragma unroll
        for (int rp = 0; rp < 8; rp++) {
            float lo, hi; UNPACK2(lo, hi, Ta[rp]);
            T_s[(rbase + 2 * rp) * 128 + c] = lo;
            T_s[(rbase + 2 * rp + 1) * 128 + c] = hi;
        }
        if (t < 32) {
            int row = t;
            float au = 0.f, av2 = 0.f;
#pragma unroll 4
            for (int f = 0; f < 112; f++) {
                float sr = stR[row * 116 + f];
                au = fmaf(sr, g_u[f], au);
                av2 = fmaf(sr, g_v[f], av2);
            }
            su[row] = au;
            sv[row] = av2;
        }
    }
    __syncthreads();

    // ---- phase 3': scores[j,i] = T[i]·states[j] + sv[i] + su[j] + c0; softmax ----
    {
        const float c0v = g_c0[0];
#pragma unroll
        for (int s2 = 0; s2 < 2; s2++) {
            int id = t + 256 * s2;
            int sbl = id >> 8, j = (id >> 4) & 15, i = id & 15;
            const float4* Tp = reinterpret_cast<const float4*>(T_s + (sbl * 16 + i) * 128);
            const float4* Sp = reinterpret_cast<const float4*>(stR + (sbl * 16 + j) * 116);
            float s0 = 0.f, s1 = 0.f, s2f = 0.f, s3 = 0.f;
#pragma unroll 7
            for (int d4 = 0; d4 < 28; d4++) {
                float4 tv = Tp[d4], sv4 = Sp[d4];
                s0 = fmaf(tv.x, sv4.x, s0); s1 = fmaf(tv.y, sv4.y, s1);
                s2f = fmaf(tv.z, sv4.z, s2f); s3 = fmaf(tv.w, sv4.w, s3);
            }
            float sc = (s0 + s1) + (s2f + s3) + sv[sbl * 16 + i] + su[sbl * 16 + j] + c0v;
            float m = sc;
#pragma unroll
            for (int o = 8; o; o >>= 1) m = fmaxf(m, __shfl_xor_sync(0xffffffffu, m, o));
            float e = __expf(sc - m);
            float sum = e;
#pragma unroll
            for (int o = 8; o; o >>= 1) sum += __shfl_xor_sync(0xffffffffu, sum, o);
            wt[(sbl * 16 + j) * 17 + i] = e / sum;
        }
    }
    __syncthreads();

    // ---- phase 2: avoff/avdiag with shared states partial (16 rows/thread) ----
    // (avoT/avdT overwrite dead T_s)
    {
        ULL sh[8];
        {
            float bvc = bv[c];
#pragma unroll
            for (int rp = 0; rp < 8; rp++) PACK2(sh[rp], bvc, bvc);
        }
#pragma unroll 4
        for (int f = 0; f < 112; f++) {
            float w = g_WvT[f * 128 + c];
            ULL w2; PACK2(w2, w, w);
            const ulonglong2* sp = reinterpret_cast<const ulonglong2*>(stT + f * 36 + rbase);
#pragma unroll
            for (int p4 = 0; p4 < 4; p4++) {
                ulonglong2 svv = sp[p4];
                FMA2(sh[2 * p4], w2, svv.x); FMA2(sh[2 * p4 + 1], w2, svv.y);
            }
        }
        // actions tail -> avoff
        {
            ULL wk_[8];
#pragma unroll
            for (int rp = 0; rp < 8; rp++) wk_[rp] = sh[rp];
#pragma unroll 4
            for (int f = 0; f < 16; f++) {
                float w = g_WvT[(112 + f) * 128 + c];
                ULL w2; PACK2(w2, w, w);
                const ulonglong2* sp = reinterpret_cast<const ulonglong2*>(actT + f * 36 + rbase);
#pragma unroll
                for (int p4 = 0; p4 < 4; p4++) {
                    ulonglong2 svv = sp[p4];
                    FMA2(wk_[2 * p4], w2, svv.x); FMA2(wk_[2 * p4 + 1], w2, svv.y);
                }
            }
            float v[16];
#pragma unroll
            for (int rp = 0; rp < 8; rp++) {
                float lo, hi; UNPACK2(lo, hi, wk_[rp]);
                TANHA(v[2 * rp], lo); TANHA(v[2 * rp + 1], hi);
            }
            float* dst = avoT + c * 36 + rbase;
#pragma unroll
            for (int p4 = 0; p4 < 4; p4++)
                *reinterpret_cast<float4*>(dst + 4 * p4) =
                    make_float4(v[4 * p4], v[4 * p4 + 1], v[4 * p4 + 2], v[4 * p4 + 3]);
        }
        // policies tail -> avdiag
        {
            ULL wk_[8];
#pragma unroll
            for (int rp = 0; rp < 8; rp++) wk_[rp] = sh[rp];
#pragma unroll 4
            for (int f = 0; f < 16; f++) {
                float w = g_WvT[(112 + f) * 128 + c];
                ULL w2; PACK2(w2, w, w);
                const ulonglong2* sp = reinterpret_cast<const ulonglong2*>(polT + f * 36 + rbase);
#pragma unroll
                for (int p4 = 0; p4 < 4; p4++) {
                    ulonglong2 svv = sp[p4];
                    FMA2(wk_[2 * p4], w2, svv.x); FMA2(wk_[2 * p4 + 1], w2, svv.y);
                }
            }
            float v[16];
#pragma unroll
            for (int rp = 0; rp < 8; rp++) {
                float lo, hi; UNPACK2(lo, hi, wk_[rp]);
                TANHA(v[2 * rp], lo); TANHA(v[2 * rp + 1], hi);
            }
            float* dst = avdT + c * 36 + rbase;
#pragma unroll
            for (int p4 = 0; p4 < 4; p4++)
                *reinterpret_cast<float4*>(dst + 4 * p4) =
                    make_float4(v[4 * p4], v[4 * p4 + 1], v[4 * p4 + 2], v[4 * p4 + 3]);
        }
    }
    __syncthreads();

    // ---- phase 4: AW1/AdW1, 2 h-columns x 8 rows per thread ----
    // (aw1/adw1 overwrite dead stT/actT/polT)
    {
        const int h = t & 31, m = (t >> 5) & 1, qd = t >> 6;  // qd in 0..3
        const int r0 = qd * 8;
        const float* srcT = m ? avdT : avoT;
        float* dst = m ? adw1 : aw1;
        ULL a0[4] = {}, a1[4] = {};
#pragma unroll 4
        for (int d = 0; d < 128; d++) {
            float w0 = g_W1T[d * 64 + h];
            float w1 = g_W1T[d * 64 + h + 32];
            ULL w02, w12; PACK2(w02, w0, w0); PACK2(w12, w1, w1);
            const ulonglong2* sp = reinterpret_cast<const ulonglong2*>(srcT + d * 36 + r0);
            ulonglong2 sv0 = sp[0], sv1 = sp[1];
            FMA2(a0[0], w02, sv0.x); FMA2(a0[1], w02, sv0.y);
            FMA2(a0[2], w02, sv1.x); FMA2(a0[3], w02, sv1.y);
            FMA2(a1[0], w12, sv0.x); FMA2(a1[1], w12, sv0.y);
            FMA2(a1[2], w12, sv1.x); FMA2(a1[3], w12, sv1.y);
        }
#pragma unroll
        for (int rp = 0; rp < 4; rp++) {
            float lo, hi;
            UNPACK2(lo, hi, a0[rp]);
            dst[(r0 + 2 * rp) * 68 + h] = lo;
            dst[(r0 + 2 * rp + 1) * 68 + h] = hi;
            UNPACK2(lo, hi, a1[rp]);
            dst[(r0 + 2 * rp) * 68 + h + 32] = lo;
            dst[(r0 + 2 * rp + 1) * 68 + h + 32] = hi;
        }
    }
    __syncthreads();

    // ---- phase 5a: SW1[ag,h] = sum_i wt[ag,i] * AW1[blr+i,h] ----
    {
        int h = t & 63, g = t >> 6, a0 = g * 8;
        int blr = (a0 >> 4) * 16;
        float acc[8] = {};
#pragma unroll
        for (int i = 0; i < 16; i++) {
            float aw_ = aw1[(blr + i) * 68 + h];
#pragma unroll
            for (int aa = 0; aa < 8; aa++)
                acc[aa] = fmaf(wt[(a0 + aa) * 17 + i], aw_, acc[aa]);
        }
#pragma unroll
        for (int aa = 0; aa < 8; aa++) sw1[(a0 + aa) * 64 + h] = acc[aa];
    }
    __syncthreads();

    // ---- phase 5b: value + weight outputs (float4 LDS) ----
    {
        int a = t >> 4, j = t & 15;
#pragma unroll
        for (int sbl = 0; sbl < 2; sbl++) {
            int ag = sbl * 16 + a, jg = sbl * 16 + j;
            float waj = wt[ag * 17 + j];
            const float4* adp = reinterpret_cast<const float4*>(adw1 + jg * 68);
            const float4* awp = reinterpret_cast<const float4*>(aw1 + jg * 68);
            const float4* swp = reinterpret_cast<const float4*>(sw1 + ag * 64);
            const float4* w2p = reinterpret_cast<const float4*>(w2s);
            float acc = 0.f;
#pragma unroll
            for (int h4 = 0; h4 < 16; h4++) {
                float4 ad = adp[h4], aw = awp[h4], swv = swp[h4], w2 = w2p[h4];
                float nf, v;
                nf = (swv.x + (ad.x - aw.x) * waj) * 0.0625f;
                v = nf > 0.f ? nf : 0.01f * nf; acc = fmaf(v, w2.x, acc);
                nf = (swv.y + (ad.y - aw.y) * waj) * 0.0625f;
                v = nf > 0.f ? nf : 0.01f * nf; acc = fmaf(v, w2.y, acc);
                nf = (swv.z + (ad.z - aw.z) * waj) * 0.0625f;
                v = nf > 0.f ? nf : 0.01f * nf; acc = fmaf(v, w2.z, acc);
                nf = (swv.w + (ad.w - aw.w) * waj) * 0.0625f;
                v = nf > 0.f ? nf : 0.01f * nf; acc = fmaf(v, w2.w, acc);
            }
            out[(b0 + sbl) * 256 + t] = acc;                  // value[b, a, j]
            if (out_size >= 262144)                            // weight[b, j, i]
                out[131072 + (b0 + sbl) * 256 + t] = wt[(sbl * 16 + (t >> 4)) * 17 + (t & 15)];
        }
    }
}

extern "C" void kernel_launch(void* const* d_in, const int* in_sizes, int n_in,
                              void* d_out, int out_size) {
    const float* states   = (const float*)d_in[0];
    const float* policies = (const float*)d_in[1];
    const float* actions  = (const float*)d_in[2];
    const float* Wk       = (const float*)d_in[3];
    const float* bk       = (const float*)d_in[4];
    const float* Wq       = (const float*)d_in[5];
    const float* bq       = (const float*)d_in[6];
    const float* Wv       = (const float*)d_in[7];
    const float* bv       = (const float*)d_in[8];
    const float* W1       = (const float*)d_in[9];
    const float* W2       = (const float*)d_in[10];
    float* out = (float*)d_out;

    cudaFuncSetAttribute(critic_kernel, cudaFuncAttributeMaxDynamicSharedMemorySize, SMEM_BYTES);

    prep<<<48, 256>>>(Wk, Wq, Wv, W1, bk, bq);
    critic_kernel<<<256, 256, SMEM_BYTES>>>(states, policies, actions,
                                            bv, W2, out, out_size);
}

// round 16
// speedup vs baseline: 1.6040x; 1.6040x over previous
#include <cuda_runtime.h>

// ---------------------------------------------------------------------------
// ScalarDotProductCriticNetworkV8 — R15: R8 with the 2 batches per CTA fully
// decoupled into independent 128-thread groups (named barriers, per-group
// smem). Warps 0-3 = batch b0, warps 4-7 = batch b0+1; groups never sync
// with each other, so their phases interleave (GEMM of one overlaps
// softmax/epilogue of the other) instead of draining 8 warps per phase.
//
// Shapes: B=512, N=16, A=16, OBS=112, D=128, H=64, F_IN=128. Grid 256 x 256.
// ---------------------------------------------------------------------------

#define ULL unsigned long long

#define PACK2(d, lo, hi) asm("mov.b64 %0, {%1, %2};" : "=l"(d) : "f"(lo), "f"(hi))
#define UNPACK2(lo, hi, v) asm("mov.b64 {%0, %1}, %2;" : "=f"(lo), "=f"(hi) : "l"(v))
#define FMA2(acc, a, b) asm("fma.rn.f32x2 %0, %1, %2, %0;" : "+l"(acc) : "l"(a), "l"(b))
#define TANHA(y, x) asm("tanh.approx.f32 %0, %1;" : "=f"(y) : "f"(x))
#define GBAR(gid) asm volatile("bar.sync %0, %1;" :: "r"((gid) + 1), "r"(128) : "memory")

// Pre-transposed weights (scratch; filled by prep kernel each launch).
__device__ float g_WkT[112 * 128];   // [kk][c]
__device__ float g_WqT[112 * 128];   // [kk][c]
__device__ float g_WvT[128 * 128];   // [f][c]
__device__ float g_W1T[128 * 64];    // [d][h]

__global__ void prep_weights(const float* __restrict__ Wk, const float* __restrict__ Wq,
                             const float* __restrict__ Wv, const float* __restrict__ W1) {
    int t = blockIdx.x * blockDim.x + threadIdx.x;
    int stride = gridDim.x * blockDim.x;
    for (int i = t; i < 112 * 128; i += stride) {
        int kk = i >> 7, c = i & 127;
        g_WkT[i] = Wk[c * 112 + kk];
        g_WqT[i] = Wq[c * 112 + kk];
    }
    for (int i = t; i < 128 * 128; i += stride) {
        int f = i >> 7, c = i & 127;
        g_WvT[i] = Wv[c * 128 + f];
    }
    for (int i = t; i < 128 * 64; i += stride) {
        int d = i >> 6, h = i & 63;
        g_W1T[i] = W1[h * 128 + d];
    }
}

// Per-group shared memory (floats). Group g in {0,1}; all regions disjoint
// across groups. Row stride 20 for 16-row transposed arrays (80B, 16B-align).
//  GA(g) = g*2880, size 2880:
//    phases 0-2: stTg[112][20]@+0, actTg[16][20]@+2240, polTg[16][20]@+2560
//    phases 4-5: aw1g[16][68]@+0 (1088), adw1g[16][68]@+1088 (ends +2176)
//  GB(g) = 5760 + g*5120, size 5120:
//    phases 1,3: k_sg[16][128]@+0 (2048), q_sg[16][132]@+2048 (ends +4160)
//    phases 2,4: avoTg[128][20]@+0 (2560), avdTg[128][20]@+2560 (ends +5120)
//  sw1g = 16000 + g*1024  [16][64]
//  wtg  = 18048 + g*272   [16][17]
//  w2s  = 18592           [64]  (written identically by both groups)
#define SMEM_FLOATS 18656
#define SMEM_BYTES  (SMEM_FLOATS * 4)

__global__ void __launch_bounds__(256, 2)
critic_kernel(const float* __restrict__ states,
              const float* __restrict__ policies,
              const float* __restrict__ actions,
              const float* __restrict__ bk,
              const float* __restrict__ bq,
              const float* __restrict__ bv,
              const float* __restrict__ W2,
              float* __restrict__ out,
              int out_size) {
    extern __shared__ float sm[];

    const int t = threadIdx.x;
    const int g = t >> 7;            // group = batch slot (0/1)
    const int lt = t & 127;          // lane within group
    const int b = blockIdx.x * 2 + g;

    float* stTg  = sm + g * 2880;
    float* actTg = stTg + 2240;
    float* polTg = stTg + 2560;
    float* aw1g  = sm + g * 2880;            // aliases stTg (dead by phase 4)
    float* adw1g = aw1g + 1088;
    float* k_sg  = sm + 5760 + g * 5120;
    float* q_sg  = k_sg + 2048;
    float* avoTg = sm + 5760 + g * 5120;     // aliases k/q (dead by phase 2)
    float* avdTg = avoTg + 2560;
    float* sw1g  = sm + 16000 + g * 1024;
    float* wtg   = sm + 18048 + g * 272;
    float* w2s   = sm + 18592;

    // ---- phase 0: load this group's batch (transposed) ----
    {
        const float* stb = states + b * (16 * 112);
        for (int idx = lt; idx < 16 * 112; idx += 128) {
            int r = idx / 112, kk = idx - r * 112;
            stTg[kk * 20 + r] = stb[idx];
        }
#pragma unroll
        for (int s = 0; s < 2; s++) {
            int idx = lt + 128 * s;              // 0..255
            int i = idx >> 4, a = idx & 15;
            actTg[a * 20 + i] = actions[b * 256 + idx];
            polTg[a * 20 + i] = policies[b * 256 + idx];
        }
        if (lt < 64) w2s[lt] = W2[lt];           // both groups write same values
    }
    GBAR(g);

    const int c = lt;                            // column 0..127

    // ---- phase 1: k AND q for the group's 16 rows ----
    {
        ULL ka[8], qa[8];
        {
            float bkc = bk[c], bqc = bq[c];
#pragma unroll
            for (int rp = 0; rp < 8; rp++) { PACK2(ka[rp], bkc, bkc); PACK2(qa[rp], bqc, bqc); }
        }
#pragma unroll 4
        for (int kk = 0; kk < 112; kk++) {
            float wk = g_WkT[kk * 128 + c];
            float wq = g_WqT[kk * 128 + c];
            ULL wk2, wq2; PACK2(wk2, wk, wk); PACK2(wq2, wq, wq);
            const ulonglong2* sp = reinterpret_cast<const ulonglong2*>(stTg + kk * 20);
#pragma unroll
            for (int p4 = 0; p4 < 4; p4++) {
                ulonglong2 sv = sp[p4];
                FMA2(ka[2 * p4], wk2, sv.x); FMA2(ka[2 * p4 + 1], wk2, sv.y);
                FMA2(qa[2 * p4], wq2, sv.x); FMA2(qa[2 * p4 + 1], wq2, sv.y);
            }
        }
        const float s = 0.08838834764831845f;  // 1/sqrt(128)
#pragma unroll
        for (int rp = 0; rp < 8; rp++) {
            float lo, hi;
            UNPACK2(lo, hi, ka[rp]);
            k_sg[(2 * rp) * 128 + c] = lo;
            k_sg[(2 * rp + 1) * 128 + c] = hi;
            UNPACK2(lo, hi, qa[rp]);
            q_sg[(2 * rp) * 132 + c] = lo * s;
            q_sg[(2 * rp + 1) * 132 + c] = hi * s;
        }
    }
    GBAR(g);

    // ---- phase 3: scores + softmax over i (16-lane shfl groups) ----
#pragma unroll
    for (int s2 = 0; s2 < 2; s2++) {
        int id = lt + 128 * s2;                  // 0..255
        int j = id >> 4, i = id & 15;
        const float4* qp = reinterpret_cast<const float4*>(q_sg + i * 132);
        const float4* kp = reinterpret_cast<const float4*>(k_sg + j * 128);
        float s0 = 0.f, s1 = 0.f, s2f = 0.f, s3 = 0.f;
#pragma unroll 8
        for (int d4 = 0; d4 < 32; d4++) {
            float4 qv = qp[d4], kv = kp[d4];
            s0 = fmaf(qv.x, kv.x, s0); s1 = fmaf(qv.y, kv.y, s1);
            s2f = fmaf(qv.z, kv.z, s2f); s3 = fmaf(qv.w, kv.w, s3);
        }
        float sc = (s0 + s1) + (s2f + s3);
        float m = sc;
#pragma unroll
        for (int o = 8; o; o >>= 1) m = fmaxf(m, __shfl_xor_sync(0xffffffffu, m, o));
        float e = __expf(sc - m);
        float sum = e;
#pragma unroll
        for (int o = 8; o; o >>= 1) sum += __shfl_xor_sync(0xffffffffu, sum, o);
        wtg[j * 17 + i] = e / sum;
    }
    GBAR(g);

    // ---- phase 2: avoff/avdiag with shared states partial (16 rows) ----
    // (avoTg/avdTg overwrite dead k_sg/q_sg — phase 3 of THIS group is done)
    {
        ULL sh[8];
        {
            float bvc = bv[c];
#pragma unroll
            for (int rp = 0; rp < 8; rp++) PACK2(sh[rp], bvc, bvc);
        }
#pragma unroll 4
        for (int f = 0; f < 112; f++) {
            float w = g_WvT[f * 128 + c];
            ULL w2; PACK2(w2, w, w);
            const ulonglong2* sp = reinterpret_cast<const ulonglong2*>(stTg + f * 20);
#pragma unroll
            for (int p4 = 0; p4 < 4; p4++) {
                ulonglong2 sv = sp[p4];
                FMA2(sh[2 * p4], w2, sv.x); FMA2(sh[2 * p4 + 1], w2, sv.y);
            }
        }
        // actions tail -> avoff
        {
            ULL wk_[8];
#pragma unroll
            for (int rp = 0; rp < 8; rp++) wk_[rp] = sh[rp];
#pragma unroll 4
            for (int f = 0; f < 16; f++) {
                float w = g_WvT[(112 + f) * 128 + c];
                ULL w2; PACK2(w2, w, w);
                const ulonglong2* sp = reinterpret_cast<const ulonglong2*>(actTg + f * 20);
#pragma unroll
                for (int p4 = 0; p4 < 4; p4++) {
                    ulonglong2 sv = sp[p4];
                    FMA2(wk_[2 * p4], w2, sv.x); FMA2(wk_[2 * p4 + 1], w2, sv.y);
                }
            }
            float v[16];
#pragma unroll
            for (int rp = 0; rp < 8; rp++) {
                float lo, hi; UNPACK2(lo, hi, wk_[rp]);
                TANHA(v[2 * rp], lo); TANHA(v[2 * rp + 1], hi);
            }
            float* dst = avoTg + c * 20;
#pragma unroll
            for (int p4 = 0; p4 < 4; p4++)
                *reinterpret_cast<float4*>(dst + 4 * p4) =
                    make_float4(v[4 * p4], v[4 * p4 + 1], v[4 * p4 + 2], v[4 * p4 + 3]);
        }
        // policies tail -> avdiag
        {
            ULL wk_[8];
#pragma unroll
            for (int rp = 0; rp < 8; rp++) wk_[rp] = sh[rp];
#pragma unroll 4
            for (int f = 0; f < 16; f++) {
                float w = g_WvT[(112 + f) * 128 + c];
                ULL w2; PACK2(w2, w, w);
                const ulonglong2* sp = reinterpret_cast<const ulonglong2*>(polTg + f * 20);
#pragma unroll
                for (int p4 = 0; p4 < 4; p4++) {
                    ulonglong2 sv = sp[p4];
                    FMA2(wk_[2 * p4], w2, sv.x); FMA2(wk_[2 * p4 + 1], w2, sv.y);
                }
            }
            float v[16];
#pragma unroll
            for (int rp = 0; rp < 8; rp++) {
                float lo, hi; UNPACK2(lo, hi, wk_[rp]);
                TANHA(v[2 * rp], lo); TANHA(v[2 * rp + 1], hi);
            }
            float* dst = avdTg + c * 20;
#pragma unroll
            for (int p4 = 0; p4 < 4; p4++)
                *reinterpret_cast<float4*>(dst + 4 * p4) =
                    make_float4(v[4 * p4], v[4 * p4 + 1], v[4 * p4 + 2], v[4 * p4 + 3]);
        }
    }
    GBAR(g);

    // ---- phase 4: AW1/AdW1, 2 h-columns x 8 rows per thread ----
    // (aw1g/adw1g overwrite dead stTg/actTg/polTg of THIS group)
    {
        const int h = lt & 31, m = (lt >> 5) & 1, qd = lt >> 6;  // qd in 0..1
        const int r0 = qd * 8;
        const float* srcT = m ? avdTg : avoTg;
        float* dst = m ? adw1g : aw1g;
        ULL a0[4] = {}, a1[4] = {};
#pragma unroll 4
        for (int d = 0; d < 128; d++) {
            float w0 = g_W1T[d * 64 + h];
            float w1 = g_W1T[d * 64 + h + 32];
            ULL w02, w12; PACK2(w02, w0, w0); PACK2(w12, w1, w1);
            const ulonglong2* sp = reinterpret_cast<const ulonglong2*>(srcT + d * 20 + r0);
            ulonglong2 sv0 = sp[0], sv1 = sp[1];
            FMA2(a0[0], w02, sv0.x); FMA2(a0[1], w02, sv0.y);
            FMA2(a0[2], w02, sv1.x); FMA2(a0[3], w02, sv1.y);
            FMA2(a1[0], w12, sv0.x); FMA2(a1[1], w12, sv0.y);
            FMA2(a1[2], w12, sv1.x); FMA2(a1[3], w12, sv1.y);
        }
#pragma unroll
        for (int rp = 0; rp < 4; rp++) {
            float lo, hi;
            UNPACK2(lo, hi, a0[rp]);
            dst[(r0 + 2 * rp) * 68 + h] = lo;
            dst[(r0 + 2 * rp + 1) * 68 + h] = hi;
            UNPACK2(lo, hi, a1[rp]);
            dst[(r0 + 2 * rp) * 68 + h + 32] = lo;
            dst[(r0 + 2 * rp + 1) * 68 + h + 32] = hi;
        }
    }
    GBAR(g);

    // ---- phase 5a: SW1[a,h] = sum_i wt[a,i] * AW1[i,h], 8 rows/thread ----
    {
        int h = lt & 63, gg = lt >> 6, a0 = gg * 8;   // gg in 0..1
        float acc[8] = {};
#pragma unroll
        for (int i = 0; i < 16; i++) {
            float aw_ = aw1g[i * 68 + h];
#pragma unroll
            for (int aa = 0; aa < 8; aa++)
                acc[aa] = fmaf(wtg[(a0 + aa) * 17 + i], aw_, acc[aa]);
        }
#pragma unroll
        for (int aa = 0; aa < 8; aa++) sw1g[(a0 + aa) * 64 + h] = acc[aa];
    }
    GBAR(g);

    // ---- phase 5b: value + weight outputs ----
#pragma unroll
    for (int s2 = 0; s2 < 2; s2++) {
        int r2 = lt + 128 * s2;                  // 0..255
        int a = r2 >> 4, j = r2 & 15;
        float waj = wtg[a * 17 + j];
        const float4* adp = reinterpret_cast<const float4*>(adw1g + j * 68);
        const float4* awp = reinterpret_cast<const float4*>(aw1g + j * 68);
        const float4* swp = reinterpret_cast<const float4*>(sw1g + a * 64);
        const float4* w2p = reinterpret_cast<const float4*>(w2s);
        float accv = 0.f;
#pragma unroll
        for (int h4 = 0; h4 < 16; h4++) {
            float4 ad = adp[h4], aw = awp[h4], swv = swp[h4], w2 = w2p[h4];
            float nf, v;
            nf = (swv.x + (ad.x - aw.x) * waj) * 0.0625f;
            v = nf > 0.f ? nf : 0.01f * nf; accv = fmaf(v, w2.x, accv);
            nf = (swv.y + (ad.y - aw.y) * waj) * 0.0625f;
            v = nf > 0.f ? nf : 0.01f * nf; accv = fmaf(v, w2.y, accv);
            nf = (swv.z + (ad.z - aw.z) * waj) * 0.0625f;
            v = nf > 0.f ? nf : 0.01f * nf; accv = fmaf(v, w2.z, accv);
            nf = (swv.w + (ad.w - aw.w) * waj) * 0.0625f;
            v = nf > 0.f ? nf : 0.01f * nf; accv = fmaf(v, w2.w, accv);
        }
        out[b * 256 + r2] = accv;                // value[b, a, j]
        if (out_size >= 262144)                  // weight[b, j_out=a, i_out=j]
            out[131072 + b * 256 + r2] = waj;
    }
}

extern "C" void kernel_launch(void* const* d_in, const int* in_sizes, int n_in,
                              void* d_out, int out_size) {
    const float* states   = (const float*)d_in[0];
    const float* policies = (const float*)d_in[1];
    const float* actions  = (const float*)d_in[2];
    const float* Wk       = (const float*)d_in[3];
    const float* bk       = (const float*)d_in[4];
    const float* Wq       = (const float*)d_in[5];
    const float* bq       = (const float*)d_in[6];
    const float* Wv       = (const float*)d_in[7];
    const float* bv       = (const float*)d_in[8];
    const float* W1       = (const float*)d_in[9];
    const float* W2       = (const float*)d_in[10];
    float* out = (float*)d_out;

    cudaFuncSetAttribute(critic_kernel, cudaFuncAttributeMaxDynamicSharedMemorySize, SMEM_BYTES);

    prep_weights<<<48, 256>>>(Wk, Wq, Wv, W1);
    critic_kernel<<<256, 256, SMEM_BYTES>>>(states, policies, actions,
                                            bk, bq, bv, W2, out, out_size);
}

// round 17
// speedup vs baseline: 1.6164x; 1.0078x over previous
#include <cuda_runtime.h>

// ---------------------------------------------------------------------------
// ScalarDotProductCriticNetworkV8 — R17 = R15 (49.9us best: decoupled
// 128-thread groups, named barriers) + two load-path cuts:
//  * Wk/Wq packed as float2 -> P1 does 112 LDG.64 instead of 224 LDG.32
//  * W1T staged into smem at phase 0 (one full-CTA syncthreads), P4 reads
//    it via LDS (29cyc) instead of L2 LDG (234cyc).
// smem 107.4KB x occ2 = 214.8KB <= 227KB.
//
// Shapes: B=512, N=16, A=16, OBS=112, D=128, H=64, F_IN=128. Grid 256 x 256.
// ---------------------------------------------------------------------------

#define ULL unsigned long long

#define PACK2(d, lo, hi) asm("mov.b64 %0, {%1, %2};" : "=l"(d) : "f"(lo), "f"(hi))
#define UNPACK2(lo, hi, v) asm("mov.b64 {%0, %1}, %2;" : "=f"(lo), "=f"(hi) : "l"(v))
#define FMA2(acc, a, b) asm("fma.rn.f32x2 %0, %1, %2, %0;" : "+l"(acc) : "l"(a), "l"(b))
#define TANHA(y, x) asm("tanh.approx.f32 %0, %1;" : "=f"(y) : "f"(x))
#define GBAR(gid) asm volatile("bar.sync %0, %1;" :: "r"((gid) + 1), "r"(128) : "memory")

// Pre-transposed weights (scratch; filled by prep kernel each launch).
__device__ float2 g_WkqT[112 * 128]; // [kk][c] = {WkT, WqT}
__device__ float  g_WvT[128 * 128];  // [f][c]
__device__ float  g_W1T[128 * 64];   // [d][h]

__global__ void prep_weights(const float* __restrict__ Wk, const float* __restrict__ Wq,
                             const float* __restrict__ Wv, const float* __restrict__ W1) {
    int t = blockIdx.x * blockDim.x + threadIdx.x;
    int stride = gridDim.x * blockDim.x;
    for (int i = t; i < 112 * 128; i += stride) {
        int kk = i >> 7, c = i & 127;
        g_WkqT[i] = make_float2(Wk[c * 112 + kk], Wq[c * 112 + kk]);
    }
    for (int i = t; i < 128 * 128; i += stride) {
        int f = i >> 7, c = i & 127;
        g_WvT[i] = Wv[c * 128 + f];
    }
    for (int i = t; i < 128 * 64; i += stride) {
        int d = i >> 6, h = i & 63;
        g_W1T[i] = W1[h * 128 + d];
    }
}

// Per-group shared memory (floats). Group g in {0,1}; regions disjoint
// across groups (same map as R15) + shared W1s at the end:
//  GA(g) = g*2880, size 2880:
//    phases 0-2: stTg[112][20]@+0, actTg[16][20]@+2240, polTg[16][20]@+2560
//    phases 4-5: aw1g[16][68]@+0, adw1g[16][68]@+1088
//  GB(g) = 5760 + g*5120, size 5120:
//    phases 1,3: k_sg[16][128]@+0, q_sg[16][132]@+2048
//    phases 2,4: avoTg[128][20]@+0, avdTg[128][20]@+2560
//  sw1g = 16000 + g*1024  [16][64]
//  wtg  = 18048 + g*272   [16][17]
//  w2s  = 18592           [64]
//  W1s  = 18656           [128*64]  (shared read-only; filled at phase 0)
#define SMEM_FLOATS (18656 + 8192)
#define SMEM_BYTES  (SMEM_FLOATS * 4)

__global__ void __launch_bounds__(256, 2)
critic_kernel(const float* __restrict__ states,
              const float* __restrict__ policies,
              const float* __restrict__ actions,
              const float* __restrict__ bk,
              const float* __restrict__ bq,
              const float* __restrict__ bv,
              const float* __restrict__ W2,
              float* __restrict__ out,
              int out_size) {
    extern __shared__ float sm[];

    const int t = threadIdx.x;
    const int g = t >> 7;            // group = batch slot (0/1)
    const int lt = t & 127;          // lane within group
    const int b = blockIdx.x * 2 + g;

    float* stTg  = sm + g * 2880;
    float* actTg = stTg + 2240;
    float* polTg = stTg + 2560;
    float* aw1g  = sm + g * 2880;            // aliases stTg (dead by phase 4)
    float* adw1g = aw1g + 1088;
    float* k_sg  = sm + 5760 + g * 5120;
    float* q_sg  = k_sg + 2048;
    float* avoTg = sm + 5760 + g * 5120;     // aliases k/q (dead by phase 2)
    float* avdTg = avoTg + 2560;
    float* sw1g  = sm + 16000 + g * 1024;
    float* wtg   = sm + 18048 + g * 272;
    float* w2s   = sm + 18592;
    float* W1s   = sm + 18656;

    // ---- phase 0: load this group's batch + stage W1T (whole CTA) ----
    {
        const float* stb = states + b * (16 * 112);
        for (int idx = lt; idx < 16 * 112; idx += 128) {
            int r = idx / 112, kk = idx - r * 112;
            stTg[kk * 20 + r] = stb[idx];
        }
#pragma unroll
        for (int s = 0; s < 2; s++) {
            int idx = lt + 128 * s;              // 0..255
            int i = idx >> 4, a = idx & 15;
            actTg[a * 20 + i] = actions[b * 256 + idx];
            polTg[a * 20 + i] = policies[b * 256 + idx];
        }
        if (lt < 64) w2s[lt] = W2[lt];           // both groups write same values
        // W1T staging: 2048 float4 across 256 threads = 8 each
#pragma unroll
        for (int w = 0; w < 8; w++) {
            int f4i = w * 256 + t;               // 0..2047
            *reinterpret_cast<float4*>(W1s + f4i * 4) =
                *reinterpret_cast<const float4*>(g_W1T + f4i * 4);
        }
    }
    __syncthreads();   // full CTA: covers W1s for both groups + own inputs

    const int c = lt;                            // column 0..127

    // ---- phase 1: k AND q for the group's 16 rows (packed LDG.64) ----
    {
        ULL ka[8], qa[8];
        {
            float bkc = bk[c], bqc = bq[c];
#pragma unroll
            for (int rp = 0; rp < 8; rp++) { PACK2(ka[rp], bkc, bkc); PACK2(qa[rp], bqc, bqc); }
        }
#pragma unroll 4
        for (int kk = 0; kk < 112; kk++) {
            float2 wkq = g_WkqT[kk * 128 + c];
            ULL wk2, wq2; PACK2(wk2, wkq.x, wkq.x); PACK2(wq2, wkq.y, wkq.y);
            const ulonglong2* sp = reinterpret_cast<const ulonglong2*>(stTg + kk * 20);
#pragma unroll
            for (int p4 = 0; p4 < 4; p4++) {
                ulonglong2 sv = sp[p4];
                FMA2(ka[2 * p4], wk2, sv.x); FMA2(ka[2 * p4 + 1], wk2, sv.y);
                FMA2(qa[2 * p4], wq2, sv.x); FMA2(qa[2 * p4 + 1], wq2, sv.y);
            }
        }
        const float s = 0.08838834764831845f;  // 1/sqrt(128)
#pragma unroll
        for (int rp = 0; rp < 8; rp++) {
            float lo, hi;
            UNPACK2(lo, hi, ka[rp]);
            k_sg[(2 * rp) * 128 + c] = lo;
            k_sg[(2 * rp + 1) * 128 + c] = hi;
            UNPACK2(lo, hi, qa[rp]);
            q_sg[(2 * rp) * 132 + c] = lo * s;
            q_sg[(2 * rp + 1) * 132 + c] = hi * s;
        }
    }
    GBAR(g);

    // ---- phase 3: scores + softmax over i (16-lane shfl groups) ----
#pragma unroll
    for (int s2 = 0; s2 < 2; s2++) {
        int id = lt + 128 * s2;                  // 0..255
        int j = id >> 4, i = id & 15;
        const float4* qp = reinterpret_cast<const float4*>(q_sg + i * 132);
        const float4* kp = reinterpret_cast<const float4*>(k_sg + j * 128);
        float s0 = 0.f, s1 = 0.f, s2f = 0.f, s3 = 0.f;
#pragma unroll 8
        for (int d4 = 0; d4 < 32; d4++) {
            float4 qv = qp[d4], kv = kp[d4];
            s0 = fmaf(qv.x, kv.x, s0); s1 = fmaf(qv.y, kv.y, s1);
            s2f = fmaf(qv.z, kv.z, s2f); s3 = fmaf(qv.w, kv.w, s3);
        }
        float sc = (s0 + s1) + (s2f + s3);
        float m = sc;
#pragma unroll
        for (int o = 8; o; o >>= 1) m = fmaxf(m, __shfl_xor_sync(0xffffffffu, m, o));
        float e = __expf(sc - m);
        float sum = e;
#pragma unroll
        for (int o = 8; o; o >>= 1) sum += __shfl_xor_sync(0xffffffffu, sum, o);
        wtg[j * 17 + i] = e / sum;
    }
    GBAR(g);

    // ---- phase 2: avoff/avdiag with shared states partial (16 rows) ----
    // (avoTg/avdTg overwrite dead k_sg/q_sg — phase 3 of THIS group is done)
    {
        ULL sh[8];
        {
            float bvc = bv[c];
#pragma unroll
            for (int rp = 0; rp < 8; rp++) PACK2(sh[rp], bvc, bvc);
        }
#pragma unroll 4
        for (int f = 0; f < 112; f++) {
            float w = g_WvT[f * 128 + c];
            ULL w2; PACK2(w2, w, w);
            const ulonglong2* sp = reinterpret_cast<const ulonglong2*>(stTg + f * 20);
#pragma unroll
            for (int p4 = 0; p4 < 4; p4++) {
                ulonglong2 sv = sp[p4];
                FMA2(sh[2 * p4], w2, sv.x); FMA2(sh[2 * p4 + 1], w2, sv.y);
            }
        }
        // actions tail -> avoff
        {
            ULL wk_[8];
#pragma unroll
            for (int rp = 0; rp < 8; rp++) wk_[rp] = sh[rp];
#pragma unroll 4
            for (int f = 0; f < 16; f++) {
                float w = g_WvT[(112 + f) * 128 + c];
                ULL w2; PACK2(w2, w, w);
                const ulonglong2* sp = reinterpret_cast<const ulonglong2*>(actTg + f * 20);
#pragma unroll
                for (int p4 = 0; p4 < 4; p4++) {
                    ulonglong2 sv = sp[p4];
                    FMA2(wk_[2 * p4], w2, sv.x); FMA2(wk_[2 * p4 + 1], w2, sv.y);
                }
            }
            float v[16];
#pragma unroll
            for (int rp = 0; rp < 8; rp++) {
                float lo, hi; UNPACK2(lo, hi, wk_[rp]);
                TANHA(v[2 * rp], lo); TANHA(v[2 * rp + 1], hi);
            }
            float* dst = avoTg + c * 20;
#pragma unroll
            for (int p4 = 0; p4 < 4; p4++)
                *reinterpret_cast<float4*>(dst + 4 * p4) =
                    make_float4(v[4 * p4], v[4 * p4 + 1], v[4 * p4 + 2], v[4 * p4 + 3]);
        }
        // policies tail -> avdiag
        {
            ULL wk_[8];
#pragma unroll
            for (int rp = 0; rp < 8; rp++) wk_[rp] = sh[rp];
#pragma unroll 4
            for (int f = 0; f < 16; f++) {
                float w = g_WvT[(112 + f) * 128 + c];
                ULL w2; PACK2(w2, w, w);
                const ulonglong2* sp = reinterpret_cast<const ulonglong2*>(polTg + f * 20);
#pragma unroll
                for (int p4 = 0; p4 < 4; p4++) {
                    ulonglong2 sv = sp[p4];
                    FMA2(wk_[2 * p4], w2, sv.x); FMA2(wk_[2 * p4 + 1], w2, sv.y);
                }
            }
            float v[16];
#pragma unroll
            for (int rp = 0; rp < 8; rp++) {
                float lo, hi; UNPACK2(lo, hi, wk_[rp]);
                TANHA(v[2 * rp], lo); TANHA(v[2 * rp + 1], hi);
            }
            float* dst = avdTg + c * 20;
#pragma unroll
            for (int p4 = 0; p4 < 4; p4++)
                *reinterpret_cast<float4*>(dst + 4 * p4) =
                    make_float4(v[4 * p4], v[4 * p4 + 1], v[4 * p4 + 2], v[4 * p4 + 3]);
        }
    }
    GBAR(g);

    // ---- phase 4: AW1/AdW1, 2 h-columns x 8 rows per thread (W1 via LDS) ----
    // (aw1g/adw1g overwrite dead stTg/actTg/polTg of THIS group)
    {
        const int h = lt & 31, m = (lt >> 5) & 1, qd = lt >> 6;  // qd in 0..1
        const int r0 = qd * 8;
        const float* srcT = m ? avdTg : avoTg;
        float* dst = m ? adw1g : aw1g;
        ULL a0[4] = {}, a1[4] = {};
#pragma unroll 4
        for (int d = 0; d < 128; d++) {
            float w0 = W1s[d * 64 + h];
            float w1 = W1s[d * 64 + h + 32];
            ULL w02, w12; PACK2(w02, w0, w0); PACK2(w12, w1, w1);
            const ulonglong2* sp = reinterpret_cast<const ulonglong2*>(srcT + d * 20 + r0);
            ulonglong2 sv0 = sp[0], sv1 = sp[1];
            FMA2(a0[0], w02, sv0.x); FMA2(a0[1], w02, sv0.y);
            FMA2(a0[2], w02, sv1.x); FMA2(a0[3], w02, sv1.y);
            FMA2(a1[0], w12, sv0.x); FMA2(a1[1], w12, sv0.y);
            FMA2(a1[2], w12, sv1.x); FMA2(a1[3], w12, sv1.y);
        }
#pragma unroll
        for (int rp = 0; rp < 4; rp++) {
            float lo, hi;
            UNPACK2(lo, hi, a0[rp]);
            dst[(r0 + 2 * rp) * 68 + h] = lo;
            dst[(r0 + 2 * rp + 1) * 68 + h] = hi;
            UNPACK2(lo, hi, a1[rp]);
            dst[(r0 + 2 * rp) * 68 + h + 32] = lo;
            dst[(r0 + 2 * rp + 1) * 68 + h + 32] = hi;
        }
    }
    GBAR(g);

    // ---- phase 5a: SW1[a,h] = sum_i wt[a,i] * AW1[i,h], 8 rows/thread ----
    {
        int h = lt & 63, gg = lt >> 6, a0 = gg * 8;   // gg in 0..1
        float acc[8] = {};
#pragma unroll
        for (int i = 0; i < 16; i++) {
            float aw_ = aw1g[i * 68 + h];
#pragma unroll
            for (int aa = 0; aa < 8; aa++)
                acc[aa] = fmaf(wtg[(a0 + aa) * 17 + i], aw_, acc[aa]);
        }
#pragma unroll
        for (int aa = 0; aa < 8; aa++) sw1g[(a0 + aa) * 64 + h] = acc[aa];
    }
    GBAR(g);

    // ---- phase 5b: value + weight outputs ----
#pragma unroll
    for (int s2 = 0; s2 < 2; s2++) {
        int r2 = lt + 128 * s2;                  // 0..255
        int a = r2 >> 4, j = r2 & 15;
        float waj = wtg[a * 17 + j];
        const float4* adp = reinterpret_cast<const float4*>(adw1g + j * 68);
        const float4* awp = reinterpret_cast<const float4*>(aw1g + j * 68);
        const float4* swp = reinterpret_cast<const float4*>(sw1g + a * 64);
        const float4* w2p = reinterpret_cast<const float4*>(w2s);
        float accv = 0.f;
#pragma unroll
        for (int h4 = 0; h4 < 16; h4++) {
            float4 ad = adp[h4], aw = awp[h4], swv = swp[h4], w2 = w2p[h4];
            float nf, v;
            nf = (swv.x + (ad.x - aw.x) * waj) * 0.0625f;
            v = nf > 0.f ? nf : 0.01f * nf; accv = fmaf(v, w2.x, accv);
            nf = (swv.y + (ad.y - aw.y) * waj) * 0.0625f;
            v = nf > 0.f ? nf : 0.01f * nf; accv = fmaf(v, w2.y, accv);
            nf = (swv.z + (ad.z - aw.z) * waj) * 0.0625f;
            v = nf > 0.f ? nf : 0.01f * nf; accv = fmaf(v, w2.z, accv);
            nf = (swv.w + (ad.w - aw.w) * waj) * 0.0625f;
            v = nf > 0.f ? nf : 0.01f * nf; accv = fmaf(v, w2.w, accv);
        }
        out[b * 256 + r2] = accv;                // value[b, a, j]
        if (out_size >= 262144)                  // weight[b, j_out=a, i_out=j]
            out[131072 + b * 256 + r2] = waj;
    }
}

extern "C" void kernel_launch(void* const* d_in, const int* in_sizes, int n_in,
                              void* d_out, int out_size) {
    const float* states   = (const float*)d_in[0];
    const float* policies = (const float*)d_in[1];
    const float* actions  = (const float*)d_in[2];
    const float* Wk       = (const float*)d_in[3];
    const float* bk       = (const float*)d_in[4];
    const float* Wq       = (const float*)d_in[5];
    const float* bq       = (const float*)d_in[6];
    const float* Wv       = (const float*)d_in[7];
    const float* bv       = (const float*)d_in[8];
    const float* W1       = (const float*)d_in[9];
    const float* W2       = (const float*)d_in[10];
    float* out = (float*)d_out;

    cudaFuncSetAttribute(critic_kernel, cudaFuncAttributeMaxDynamicSharedMemorySize, SMEM_BYTES);

    prep_weights<<<48, 256>>>(Wk, Wq, Wv, W1);
    critic_kernel<<<256, 256, SMEM_BYTES>>>(states, policies, actions,
                                            bk, bq, bv, W2, out, out_size);
}